// round 3
// baseline (speedup 1.0000x reference)
#include <cuda_runtime.h>
#include <math.h>

#define B_ 8
#define L_ 1024
#define D_ 256
#define U_ 256

typedef unsigned long long ull;

// ---------------- scratch (device globals; no allocation allowed) ----------
__device__ float g_EW[D_ * U_];          // E @ Wx            (256 KB)
__device__ float g_rnorm[B_ * L_];       // 1/max(rowsum,eps) (32 KB)
__device__ float g_t[B_ * L_ * U_];      // (seq@EW)*rnorm    (8 MB)
__device__ float g_xproj[B_ * L_ * U_];  // G^T @ t           (8 MB)

// ---------------- packed f32x2 helpers (sm_103a) ----------------------------
__device__ __forceinline__ ull pk2(float lo, float hi) {
    ull r; asm("mov.b64 %0,{%1,%2};" : "=l"(r) : "f"(lo), "f"(hi)); return r;
}
__device__ __forceinline__ void ffma2(ull& d, ull a, ull b) {
    asm("fma.rn.f32x2 %0,%1,%2,%0;" : "+l"(d) : "l"(a), "l"(b));
}
__device__ __forceinline__ float2 up2(ull a) {
    float lo, hi; asm("mov.b64 {%0,%1},%2;" : "=f"(lo), "=f"(hi) : "l"(a));
    float2 r; r.x = lo; r.y = hi; return r;
}
// tanh(z) = 1 - 2/(1+exp(2z)) with MUFU ex2/rcp (rel err ~1e-6)
__device__ __forceinline__ float fast_tanh(float z) {
    float t2 = z * 2.885390081777927f;  // 2*log2(e)
    float ex; asm("ex2.approx.f32 %0,%1;" : "=f"(ex) : "f"(t2));
    float den = ex + 1.0f;
    float rc; asm("rcp.approx.f32 %0,%1;" : "=f"(rc) : "f"(den));
    return fmaf(-2.0f, rc, 1.0f);
}

// ---------------- 1) rnorm[b,l] = 1 / max(sum_m graph[b,l,m], 1e-7) ---------
__global__ __launch_bounds__(256) void norm_kernel(const float* __restrict__ graph,
                                                   float* __restrict__ rnorm) {
    int warp = (blockIdx.x * blockDim.x + threadIdx.x) >> 5;
    int lane = threadIdx.x & 31;
    if (warp >= B_ * L_) return;
    const float4* row = (const float4*)(graph + (size_t)warp * L_);
    float s = 0.f;
#pragma unroll
    for (int i = lane; i < L_ / 4; i += 32) {
        float4 v = row[i];
        s += (v.x + v.y) + (v.z + v.w);
    }
#pragma unroll
    for (int o = 16; o; o >>= 1) s += __shfl_xor_sync(0xffffffffu, s, o);
    if (lane == 0) rnorm[warp] = 1.f / fmaxf(s, 1e-7f);
}

// ---------------- 2) GEMM NN: C[M,N] = A[M,K] @ B[K,N] (* rowscale) ---------
__global__ __launch_bounds__(256) void gemm_nn(const float* __restrict__ A,
                                               const float* __restrict__ Bm,
                                               float* __restrict__ C, int K,
                                               const float* __restrict__ rowscale) {
    __shared__ float As[2][16][128];
    __shared__ float Bs[2][16][128];
    const int N = 256;
    const int m0 = blockIdx.y * 128, n0 = blockIdx.x * 128;
    const int t = threadIdx.x;
    const int tx = t & 15, ty = t >> 4;

    ull acc[8][4];
#pragma unroll
    for (int i = 0; i < 8; i++)
#pragma unroll
        for (int j = 0; j < 4; j++) acc[i][j] = 0ull;

    int am[2], akg[2], bkk[2], bng[2];
#pragma unroll
    for (int i = 0; i < 2; i++) {
        int f4 = t + i * 256;
        am[i] = f4 >> 2; akg[i] = f4 & 3;
        bkk[i] = f4 >> 5; bng[i] = f4 & 31;
    }

    float4 ra[2], rb[2];
#pragma unroll
    for (int i = 0; i < 2; i++) {
        ra[i] = *(const float4*)(A + (size_t)(m0 + am[i]) * K + akg[i] * 4);
        rb[i] = *(const float4*)(Bm + (size_t)bkk[i] * N + n0 + bng[i] * 4);
    }

    int cur = 0;
    for (int k0 = 0; k0 < K; k0 += 16) {
#pragma unroll
        for (int i = 0; i < 2; i++) {
            As[cur][akg[i] * 4 + 0][am[i]] = ra[i].x;
            As[cur][akg[i] * 4 + 1][am[i]] = ra[i].y;
            As[cur][akg[i] * 4 + 2][am[i]] = ra[i].z;
            As[cur][akg[i] * 4 + 3][am[i]] = ra[i].w;
            *(float4*)&Bs[cur][bkk[i]][bng[i] * 4] = rb[i];
        }
        __syncthreads();
        if (k0 + 16 < K) {
#pragma unroll
            for (int i = 0; i < 2; i++) {
                ra[i] = *(const float4*)(A + (size_t)(m0 + am[i]) * K + k0 + 16 + akg[i] * 4);
                rb[i] = *(const float4*)(Bm + (size_t)(k0 + 16 + bkk[i]) * N + n0 + bng[i] * 4);
            }
        }
#pragma unroll
        for (int kk = 0; kk < 16; kk++) {
            float4 a0 = *(float4*)&As[cur][kk][ty * 8];
            float4 a1 = *(float4*)&As[cur][kk][ty * 8 + 4];
            float4 b0 = *(float4*)&Bs[cur][kk][tx * 8];
            float4 b1 = *(float4*)&Bs[cur][kk][tx * 8 + 4];
            ull bp0 = pk2(b0.x, b0.y), bp1 = pk2(b0.z, b0.w);
            ull bp2 = pk2(b1.x, b1.y), bp3 = pk2(b1.z, b1.w);
            float av[8] = {a0.x, a0.y, a0.z, a0.w, a1.x, a1.y, a1.z, a1.w};
#pragma unroll
            for (int i = 0; i < 8; i++) {
                ull ad = pk2(av[i], av[i]);
                ffma2(acc[i][0], ad, bp0);
                ffma2(acc[i][1], ad, bp1);
                ffma2(acc[i][2], ad, bp2);
                ffma2(acc[i][3], ad, bp3);
            }
        }
        cur ^= 1;
    }
#pragma unroll
    for (int i = 0; i < 8; i++) {
        int row = m0 + ty * 8 + i;
        float sc = rowscale ? rowscale[row] : 1.f;
        float2 v0 = up2(acc[i][0]), v1 = up2(acc[i][1]);
        float2 v2 = up2(acc[i][2]), v3 = up2(acc[i][3]);
        float4 o0 = make_float4(v0.x * sc, v0.y * sc, v1.x * sc, v1.y * sc);
        float4 o1 = make_float4(v2.x * sc, v2.y * sc, v3.x * sc, v3.y * sc);
        *(float4*)(C + (size_t)row * N + n0 + tx * 8) = o0;
        *(float4*)(C + (size_t)row * N + n0 + tx * 8 + 4) = o1;
    }
}

// ---------------- 3) GEMM TN (per batch): C[m,u] = sum_l G[l,m] * t[l,u] ----
__global__ __launch_bounds__(256) void gemm_tn(const float* __restrict__ A,
                                               const float* __restrict__ Bm,
                                               float* __restrict__ C) {
    __shared__ float As[2][16][128];
    __shared__ float Bs[2][16][128];
    const int N = 256, K = L_, lda = L_;
    const int b = blockIdx.z;
    A += (size_t)b * L_ * L_;
    Bm += (size_t)b * L_ * U_;
    C += (size_t)b * L_ * U_;
    const int m0 = blockIdx.y * 128, n0 = blockIdx.x * 128;
    const int t = threadIdx.x;
    const int tx = t & 15, ty = t >> 4;

    ull acc[8][4];
#pragma unroll
    for (int i = 0; i < 8; i++)
#pragma unroll
        for (int j = 0; j < 4; j++) acc[i][j] = 0ull;

    int kk_[2], g_[2];
#pragma unroll
    for (int i = 0; i < 2; i++) {
        int f4 = t + i * 256;
        kk_[i] = f4 >> 5; g_[i] = f4 & 31;
    }

    float4 ra[2], rb[2];
#pragma unroll
    for (int i = 0; i < 2; i++) {
        ra[i] = *(const float4*)(A + (size_t)kk_[i] * lda + m0 + g_[i] * 4);
        rb[i] = *(const float4*)(Bm + (size_t)kk_[i] * N + n0 + g_[i] * 4);
    }

    int cur = 0;
    for (int k0 = 0; k0 < K; k0 += 16) {
#pragma unroll
        for (int i = 0; i < 2; i++) {
            *(float4*)&As[cur][kk_[i]][g_[i] * 4] = ra[i];
            *(float4*)&Bs[cur][kk_[i]][g_[i] * 4] = rb[i];
        }
        __syncthreads();
        if (k0 + 16 < K) {
#pragma unroll
            for (int i = 0; i < 2; i++) {
                ra[i] = *(const float4*)(A + (size_t)(k0 + 16 + kk_[i]) * lda + m0 + g_[i] * 4);
                rb[i] = *(const float4*)(Bm + (size_t)(k0 + 16 + kk_[i]) * N + n0 + g_[i] * 4);
            }
        }
#pragma unroll
        for (int kk = 0; kk < 16; kk++) {
            float4 a0 = *(float4*)&As[cur][kk][ty * 8];
            float4 a1 = *(float4*)&As[cur][kk][ty * 8 + 4];
            float4 b0 = *(float4*)&Bs[cur][kk][tx * 8];
            float4 b1 = *(float4*)&Bs[cur][kk][tx * 8 + 4];
            ull bp0 = pk2(b0.x, b0.y), bp1 = pk2(b0.z, b0.w);
            ull bp2 = pk2(b1.x, b1.y), bp3 = pk2(b1.z, b1.w);
            float av[8] = {a0.x, a0.y, a0.z, a0.w, a1.x, a1.y, a1.z, a1.w};
#pragma unroll
            for (int i = 0; i < 8; i++) {
                ull ad = pk2(av[i], av[i]);
                ffma2(acc[i][0], ad, bp0);
                ffma2(acc[i][1], ad, bp1);
                ffma2(acc[i][2], ad, bp2);
                ffma2(acc[i][3], ad, bp3);
            }
        }
        cur ^= 1;
    }
#pragma unroll
    for (int i = 0; i < 8; i++) {
        int row = m0 + ty * 8 + i;
        float2 v0 = up2(acc[i][0]), v1 = up2(acc[i][1]);
        float2 v2 = up2(acc[i][2]), v3 = up2(acc[i][3]);
        float4 o0 = make_float4(v0.x, v0.y, v1.x, v1.y);
        float4 o1 = make_float4(v2.x, v2.y, v3.x, v3.y);
        *(float4*)(C + (size_t)row * N + n0 + tx * 8) = o0;
        *(float4*)(C + (size_t)row * N + n0 + tx * 8 + 4) = o1;
    }
}

// ---------------- 4) sequential scan: h = tanh(xproj[s] + h @ Wh + b) -------
// One CTA per batch, 256 threads = 8 warps.
// Lane l = kq*8 + r (kq = k-slice of 64, r = output group).
// Thread outputs: u = w*32 + r*4 + j (j=0..3); k in [kq*64, kq*64+64).
// Per (output, k-slice): 32 weight pairs -> 26 in RF, 6 in SMEM.
// Cross-kq reduction via shfl.bfly(8), shfl.bfly(16). ONE barrier per step.
#define RF_PAIRS 26
#define SM_PAIRS 6
#define WS_ULLS (SM_PAIRS * 4 * 8 * 32)          // 6144 ull = 48 KB
#define SCAN_SMEM_BYTES (WS_ULLS * 8 + 2 * 256 * 4)

__global__ __launch_bounds__(256, 1) void scan_kernel(const float* __restrict__ Wh,
                                                      const float* __restrict__ xproj,
                                                      const float* __restrict__ bias,
                                                      float* __restrict__ out) {
    extern __shared__ unsigned char smraw[];
    ull* ws = (ull*)smraw;                           // 48 KB SMEM weights
    float* hbuf = (float*)(smraw + WS_ULLS * 8);     // 2 KB h (double buffer)

    const int tid = threadIdx.x;
    const int b = blockIdx.x;
    const int w = tid >> 5, l = tid & 31;
    const int kq = l >> 3, r = l & 7;
    const int u0 = w * 32 + r * 4;

    // SMEM weights: ws[((ps*4 + j)*8 + w)*32 + l] = pair(k, k+1) for output
    // u = w*32 + (l&7)*4 + j, k = (l>>3)*64 + 2*(RF_PAIRS + ps)
    for (int idx = tid; idx < WS_ULLS; idx += 256) {
        int lf = idx & 31;
        int rest = idx >> 5;
        int wf = rest & 7;
        int rest2 = rest >> 3;
        int jf = rest2 & 3;
        int ps = rest2 >> 2;
        int uf = wf * 32 + (lf & 7) * 4 + jf;
        int kf = (lf >> 3) * 64 + 2 * (RF_PAIRS + ps);
        ws[idx] = pk2(Wh[kf * U_ + uf], Wh[(kf + 1) * U_ + uf]);
    }

    // RF weights: wreg[j][p] = pair(k = kq*64 + 2p) for output u0+j
    ull wreg[4][RF_PAIRS];
#pragma unroll
    for (int j = 0; j < 4; j++)
#pragma unroll
        for (int p = 0; p < RF_PAIRS; p++) {
            int k = kq * 64 + 2 * p;
            wreg[j][p] = pk2(Wh[k * U_ + u0 + j], Wh[(k + 1) * U_ + u0 + j]);
        }

    hbuf[tid] = 0.f;
    hbuf[256 + tid] = 0.f;

    const bool leader = (kq == 0);
    float4 bv4 = *(const float4*)(bias + u0);
    const float* xbase = xproj + (size_t)b * L_ * U_ + u0;
    float* obase = out + (size_t)b * L_ * U_ + u0;
    float4 xv4 = *(const float4*)xbase;
    int cur = 0;
    __syncthreads();

    const ull* wsp = ws + w * 32 + l;

    for (int s = 0; s < L_; s++) {
        // prefetch next x (leader lanes only)
        float4 xn4;
        if (leader) {
            int sn = (s + 1 < L_) ? s + 1 : s;
            xn4 = *(const float4*)(xbase + (size_t)sn * U_);
        }

        const ulonglong2* hp2 = (const ulonglong2*)(hbuf + cur * 256 + kq * 64);
        ull a0 = 0ull, a1 = 0ull, a2 = 0ull, a3 = 0ull;
#pragma unroll
        for (int q = 0; q < 13; q++) {   // RF pairs 0..25
            ulonglong2 hv = hp2[q];
            ffma2(a0, hv.x, wreg[0][2 * q]);
            ffma2(a1, hv.x, wreg[1][2 * q]);
            ffma2(a2, hv.x, wreg[2][2 * q]);
            ffma2(a3, hv.x, wreg[3][2 * q]);
            ffma2(a0, hv.y, wreg[0][2 * q + 1]);
            ffma2(a1, hv.y, wreg[1][2 * q + 1]);
            ffma2(a2, hv.y, wreg[2][2 * q + 1]);
            ffma2(a3, hv.y, wreg[3][2 * q + 1]);
        }
#pragma unroll
        for (int qq = 0; qq < 3; qq++) { // SMEM pairs 26..31
            ulonglong2 hv = hp2[13 + qq];
            int ps0 = 2 * qq, ps1 = 2 * qq + 1;
            ffma2(a0, hv.x, wsp[(ps0 * 4 + 0) * 256]);
            ffma2(a1, hv.x, wsp[(ps0 * 4 + 1) * 256]);
            ffma2(a2, hv.x, wsp[(ps0 * 4 + 2) * 256]);
            ffma2(a3, hv.x, wsp[(ps0 * 4 + 3) * 256]);
            ffma2(a0, hv.y, wsp[(ps1 * 4 + 0) * 256]);
            ffma2(a1, hv.y, wsp[(ps1 * 4 + 1) * 256]);
            ffma2(a2, hv.y, wsp[(ps1 * 4 + 2) * 256]);
            ffma2(a3, hv.y, wsp[(ps1 * 4 + 3) * 256]);
        }
        float2 v0 = up2(a0), v1 = up2(a1), v2 = up2(a2), v3 = up2(a3);
        float f0 = v0.x + v0.y, f1 = v1.x + v1.y;
        float f2 = v2.x + v2.y, f3 = v3.x + v3.y;
        // cross-kq reduction (lanes l, l^8, l^16, l^24)
        f0 += __shfl_xor_sync(0xffffffffu, f0, 8);
        f1 += __shfl_xor_sync(0xffffffffu, f1, 8);
        f2 += __shfl_xor_sync(0xffffffffu, f2, 8);
        f3 += __shfl_xor_sync(0xffffffffu, f3, 8);
        f0 += __shfl_xor_sync(0xffffffffu, f0, 16);
        f1 += __shfl_xor_sync(0xffffffffu, f1, 16);
        f2 += __shfl_xor_sync(0xffffffffu, f2, 16);
        f3 += __shfl_xor_sync(0xffffffffu, f3, 16);

        if (leader) {
            float4 h4;
            h4.x = fast_tanh(f0 + xv4.x + bv4.x);
            h4.y = fast_tanh(f1 + xv4.y + bv4.y);
            h4.z = fast_tanh(f2 + xv4.z + bv4.z);
            h4.w = fast_tanh(f3 + xv4.w + bv4.w);
            *(float4*)&hbuf[(cur ^ 1) * 256 + u0] = h4;
            *(float4*)(obase + (size_t)s * U_) = h4;
            xv4 = xn4;
        }
        cur ^= 1;
        __syncthreads();
    }
}

// ---------------- launch --------------------------------------------------
extern "C" void kernel_launch(void* const* d_in, const int* in_sizes, int n_in,
                              void* d_out, int out_size) {
    const float* seq = (const float*)d_in[0];    // (8,1024,256)
    const float* graph = (const float*)d_in[1];  // (8,1024,1024)
    const float* E = (const float*)d_in[2];      // (256,256)
    const float* Wx = (const float*)d_in[3];     // (256,256)
    const float* Wh = (const float*)d_in[4];     // (256,256)
    const float* bias = (const float*)d_in[5];   // (256,)
    float* out = (float*)d_out;                  // (8,1024,256)

    float *ew, *rn, *tt, *xp;
    cudaGetSymbolAddress((void**)&ew, g_EW);
    cudaGetSymbolAddress((void**)&rn, g_rnorm);
    cudaGetSymbolAddress((void**)&tt, g_t);
    cudaGetSymbolAddress((void**)&xp, g_xproj);

    norm_kernel<<<(B_ * L_) / 8, 256>>>(graph, rn);
    gemm_nn<<<dim3(2, 2), 256>>>(E, Wx, ew, 256, nullptr);
    gemm_nn<<<dim3(2, 64), 256>>>(seq, ew, tt, 256, rn);
    gemm_tn<<<dim3(2, 8, 8), 256>>>(graph, tt, xp);
    cudaFuncSetAttribute(scan_kernel, cudaFuncAttributeMaxDynamicSharedMemorySize,
                         SCAN_SMEM_BYTES);
    scan_kernel<<<B_, 256, SCAN_SMEM_BYTES>>>(Wh, xp, bias, out);
}